// round 16
// baseline (speedup 1.0000x reference)
#include <cuda_runtime.h>
#include <cuda_bf16.h>

// y[i,a,b] = sum_{kj,kh,l} w[i,kj,kh,l] * U[a+kj-1, kh, b, l]   (zero pad on a+kj-1)
// U[ap,kh,b,l] = T(ap,kh,(b-1)%14, l+128) + T(ap,kh,b,l)
// T(ap,kh,b',c) = (0 <= b'+kh-1 < 14) ? x[c, ap, (b'+kh-2) mod 14] : 0
// w natural k-linearization k = kj*384 + kh*128 + l matches u_s layout.

#define U_ELEMS (14 * 3 * 14 * 128)     // 75264
#define U_BLOCKS 294                     // 294*256 == 75264

__device__ float g_U[U_ELEMS];          // [ap][kh][b][l]

__global__ void prep_kernel(const float* __restrict__ x) {
    int e = blockIdx.x * 256 + threadIdx.x;          // < 75264
    int l  = e & 127;
    int b  = (e >> 7) % 14;
    int kh = (e / (128 * 14)) % 3;
    int ap = e / (128 * 14 * 3);

    float val = 0.0f;
    int t = b + kh - 1;
    if (t >= 0 && t < 14) {
        int wsrc = t - 1; if (wsrc < 0) wsrc += 14;
        val += x[l * 196 + ap * 14 + wsrc];
    }
    int bm = b - 1; if (bm < 0) bm += 14;
    int t1 = bm + kh - 1;
    if (t1 >= 0 && t1 < 14) {
        int wsrc = t1 - 1; if (wsrc < 0) wsrc += 14;
        val += x[(l + 128) * 196 + ap * 14 + wsrc];
    }
    g_U[e] = val;
}

// Grid (a=14, i-tile=8, b-quad=4) = 448 blocks (~3/SM, smooth distribution).
// b-quads overlap: b0 = min(h0*4, 10); overlapped b recompute identical y (benign).
// Block 256 = 8 warps = 8 channel-quads, full K=1152.
// Lane owns k = j*128 + lane*4 + {0..3}, j=0..8.  LDG.128 w + LDS.128 u give two
// k-parity f32x2 pairs each -> 4 LDG + 4 LDS + 32 FFMA2 per j, zero packing movs.
// acc2[4][4] = 32 regs; __launch_bounds__(256,3) -> 3 blocks/SM, 24 warps/SM.
__global__ __launch_bounds__(256, 3)
void gemm_kernel(const float* __restrict__ w, float* __restrict__ y) {
    __shared__ float u_s[4608];          // [bb=4][k=1152] = 18432B; reused: red[128][33]

    const int a   = blockIdx.x;          // 0..13
    const int i0  = blockIdx.y * 32;
    const int b0  = min((int)blockIdx.z * 4, 10);
    const int tid = threadIdx.x;

    // ---- stage u_s[bb][kj*384+kh*128+l] from g_U rows ap = a-1..a+1 ----
    float4* u4s = (float4*)u_s;
#pragma unroll
    for (int it = 0; it < 5; it++) {
        int idx = it * 256 + tid;                    // < 1280; valid < 1152
        if (idx < 1152) {
            int bb = idx / 288;                      // 1152/4
            int r  = idx - bb * 288;
            int kj = r / 96;
            int r2 = r - kj * 96;                    // kh*32 + l4
            int ap = a - 1 + kj;
            float4 v = make_float4(0.f, 0.f, 0.f, 0.f);
            if (ap >= 0 && ap < 14)
                v = ((const float4*)g_U)[ap * 1344 + (r2 >> 5) * 448
                                         + (b0 + bb) * 32 + (r2 & 31)];
            u4s[idx] = v;
        }
    }
    __syncthreads();

    const int g    = tid >> 5;           // warp = channel quad 0..7
    const int lane = tid & 31;
    const int ch0  = i0 + g * 4;

    unsigned long long acc2[4][4];       // [c][bb]; lo = even-k partial, hi = odd-k
#pragma unroll
    for (int c = 0; c < 4; c++)
#pragma unroll
        for (int bb = 0; bb < 4; bb++) acc2[c][bb] = 0ull;

    // natural-layout w rows: 288 ulonglong2 (k-quads) per channel, coalesced LDG.128
    const ulonglong2* pw0 = (const ulonglong2*)w + (ch0 + 0) * 288 + lane;
    const ulonglong2* pw1 = (const ulonglong2*)w + (ch0 + 1) * 288 + lane;
    const ulonglong2* pw2 = (const ulonglong2*)w + (ch0 + 2) * 288 + lane;
    const ulonglong2* pw3 = (const ulonglong2*)w + (ch0 + 3) * 288 + lane;
    const ulonglong2* pu  = (const ulonglong2*)u_s + lane;

#pragma unroll 3
    for (int j = 0; j < 9; j++) {
        ulonglong2 wv0 = pw0[j * 32];
        ulonglong2 wv1 = pw1[j * 32];
        ulonglong2 wv2 = pw2[j * 32];
        ulonglong2 wv3 = pw3[j * 32];
#pragma unroll
        for (int bb = 0; bb < 4; bb++) {
            ulonglong2 uv = pu[bb * 288 + j * 32];   // LDS.128, serves 4 channels
            asm("fma.rn.f32x2 %0, %1, %2, %0;" : "+l"(acc2[0][bb]) : "l"(wv0.x), "l"(uv.x));
            asm("fma.rn.f32x2 %0, %1, %2, %0;" : "+l"(acc2[1][bb]) : "l"(wv1.x), "l"(uv.x));
            asm("fma.rn.f32x2 %0, %1, %2, %0;" : "+l"(acc2[2][bb]) : "l"(wv2.x), "l"(uv.x));
            asm("fma.rn.f32x2 %0, %1, %2, %0;" : "+l"(acc2[3][bb]) : "l"(wv3.x), "l"(uv.x));
            asm("fma.rn.f32x2 %0, %1, %2, %0;" : "+l"(acc2[0][bb]) : "l"(wv0.y), "l"(uv.y));
            asm("fma.rn.f32x2 %0, %1, %2, %0;" : "+l"(acc2[1][bb]) : "l"(wv1.y), "l"(uv.y));
            asm("fma.rn.f32x2 %0, %1, %2, %0;" : "+l"(acc2[2][bb]) : "l"(wv2.y), "l"(uv.y));
            asm("fma.rn.f32x2 %0, %1, %2, %0;" : "+l"(acc2[3][bb]) : "l"(wv3.y), "l"(uv.y));
        }
    }

    __syncthreads();                                 // u_s reusable as red buffer
    float* red = u_s;                                // red[out][33], out = (g*4+c)*4+bb
#pragma unroll
    for (int c = 0; c < 4; c++)
#pragma unroll
        for (int bb = 0; bb < 4; bb++) {
            float lo, hi;
            asm("mov.b64 {%0, %1}, %2;" : "=f"(lo), "=f"(hi) : "l"(acc2[c][bb]));
            red[((g * 4 + c) * 4 + bb) * 33 + lane] = lo + hi;
        }
    __syncthreads();

    if (tid < 128) {
        const float* rf = red + tid * 33;
        float s0 = 0.f, s1 = 0.f, s2 = 0.f, s3 = 0.f;
#pragma unroll
        for (int q = 0; q < 32; q += 4) {
            s0 += rf[q + 0];
            s1 += rf[q + 1];
            s2 += rf[q + 2];
            s3 += rf[q + 3];
        }
        float sum = (s0 + s1) + (s2 + s3);
        int gc = tid >> 2;               // g*4+c (channel within tile)
        int bb = tid & 3;
        y[(i0 + gc) * 196 + a * 14 + b0 + bb] = sum;   // overlap stores identical values
    }
}

extern "C" void kernel_launch(void* const* d_in, const int* in_sizes, int n_in,
                              void* d_out, int out_size) {
    const float* x = (const float*)d_in[0];
    const float* w = (const float*)d_in[1];
    float* y = (float*)d_out;

    prep_kernel<<<U_BLOCKS, 256>>>(x);
    gemm_kernel<<<dim3(14, 8, 4), 256>>>(w, y);
}

// round 17
// speedup vs baseline: 1.0200x; 1.0200x over previous
#include <cuda_runtime.h>
#include <cuda_bf16.h>

// y[i,a,b] = sum_{kj,kh,l} w[i,kj,kh,l] * U[a+kj-1, kh, b, l]   (zero pad on a+kj-1)
// U[ap,kh,b,l] = T(ap,kh,(b-1)%14, l+128) + T(ap,kh,b,l)
// T(ap,kh,b',c) = (0 <= b'+kh-1 < 14) ? x[c, ap, (b'+kh-2) mod 14] : 0
// w natural k-linearization k = kj*384 + kh*128 + l.

#define U_ELEMS (14 * 3 * 14 * 128)     // 75264
#define U_BLOCKS 294                     // 294*256 == 75264

__device__ float g_U[U_ELEMS];          // [ap][kh=3][b=14][l=128]
__device__ float g_zero[4480];          // static zero-init; never written (pad reads)

__global__ void prep_kernel(const float* __restrict__ x) {
    int e = blockIdx.x * 256 + threadIdx.x;          // < 75264
    int l  = e & 127;
    int b  = (e >> 7) % 14;
    int kh = (e / (128 * 14)) % 3;
    int ap = e / (128 * 14 * 3);

    float val = 0.0f;
    int t = b + kh - 1;
    if (t >= 0 && t < 14) {
        int wsrc = t - 1; if (wsrc < 0) wsrc += 14;
        val += x[l * 196 + ap * 14 + wsrc];
    }
    int bm = b - 1; if (bm < 0) bm += 14;
    int t1 = bm + kh - 1;
    if (t1 >= 0 && t1 < 14) {
        int wsrc = t1 - 1; if (wsrc < 0) wsrc += 14;
        val += x[(l + 128) * 196 + ap * 14 + wsrc];
    }
    g_U[e] = val;
}

// Grid (a=14, i-tile=8, b-half=2) = 224 blocks. Block 256 = 8 warps = 8 channel-quads.
// Lane owns k = j*128 + lane*4 + {0..3}, j=0..8 (kj=j/3, kh=j%3, l=lane*4).
// u read DIRECTLY from g_U: coalesced LDG.128 (512B/warp), L1-resident after first
// touch (32KB/block). No staging, no smem crossbar, no pre-loop barrier.
// Out-of-range ap (padding) -> base pointer redirected to zeroed g_zero.
// k-parity f32x2 accumulation; acc2[4][7] = 56 regs.
__global__ __launch_bounds__(256, 2)
void gemm_kernel(const float* __restrict__ w, float* __restrict__ y) {
    __shared__ float red[224 * 33];      // epilogue only: [out][33], 29568 B

    const int a   = blockIdx.x;          // 0..13
    const int i0  = blockIdx.y * 32;
    const int h0  = blockIdx.z;          // b = h0*7 + bb
    const int tid = threadIdx.x;
    const int g    = tid >> 5;           // warp = channel quad 0..7
    const int lane = tid & 31;
    const int ch0  = i0 + g * 4;

    // per-kj u base pointers (zero-page redirect outside [0,14))
    const float* ub[3];
#pragma unroll
    for (int kj = 0; kj < 3; kj++) {
        int ap = a - 1 + kj;
        ub[kj] = (ap >= 0 && ap < 14) ? (g_U + ap * 5376 + h0 * 7 * 128) : g_zero;
    }

    unsigned long long acc2[4][7];       // [c][bb]; lo = even-k partial, hi = odd-k
#pragma unroll
    for (int c = 0; c < 4; c++)
#pragma unroll
        for (int bb = 0; bb < 7; bb++) acc2[c][bb] = 0ull;

    // natural-layout w rows: 288 ulonglong2 (k-quads) per channel, coalesced LDG.128
    const ulonglong2* pw0 = (const ulonglong2*)w + (ch0 + 0) * 288 + lane;
    const ulonglong2* pw1 = (const ulonglong2*)w + (ch0 + 1) * 288 + lane;
    const ulonglong2* pw2 = (const ulonglong2*)w + (ch0 + 2) * 288 + lane;
    const ulonglong2* pw3 = (const ulonglong2*)w + (ch0 + 3) * 288 + lane;

#pragma unroll 3
    for (int j = 0; j < 9; j++) {
        ulonglong2 wv0 = pw0[j * 32];
        ulonglong2 wv1 = pw1[j * 32];
        ulonglong2 wv2 = pw2[j * 32];
        ulonglong2 wv3 = pw3[j * 32];
        // u address: ub[j/3] + (j%3)*1792 + bb*128 + lane*4  (coalesced LDG.128)
        const float* uj = ub[j / 3] + (j % 3) * 1792 + lane * 4;
#pragma unroll
        for (int bb = 0; bb < 7; bb++) {
            ulonglong2 uv = *(const ulonglong2*)(uj + bb * 128);
            asm("fma.rn.f32x2 %0, %1, %2, %0;" : "+l"(acc2[0][bb]) : "l"(wv0.x), "l"(uv.x));
            asm("fma.rn.f32x2 %0, %1, %2, %0;" : "+l"(acc2[1][bb]) : "l"(wv1.x), "l"(uv.x));
            asm("fma.rn.f32x2 %0, %1, %2, %0;" : "+l"(acc2[2][bb]) : "l"(wv2.x), "l"(uv.x));
            asm("fma.rn.f32x2 %0, %1, %2, %0;" : "+l"(acc2[3][bb]) : "l"(wv3.x), "l"(uv.x));
            asm("fma.rn.f32x2 %0, %1, %2, %0;" : "+l"(acc2[0][bb]) : "l"(wv0.y), "l"(uv.y));
            asm("fma.rn.f32x2 %0, %1, %2, %0;" : "+l"(acc2[1][bb]) : "l"(wv1.y), "l"(uv.y));
            asm("fma.rn.f32x2 %0, %1, %2, %0;" : "+l"(acc2[2][bb]) : "l"(wv2.y), "l"(uv.y));
            asm("fma.rn.f32x2 %0, %1, %2, %0;" : "+l"(acc2[3][bb]) : "l"(wv3.y), "l"(uv.y));
        }
    }

    // ---- epilogue: per-lane partials -> smem -> 224 output sums ----
#pragma unroll
    for (int c = 0; c < 4; c++)
#pragma unroll
        for (int bb = 0; bb < 7; bb++) {
            float lo, hi;
            asm("mov.b64 {%0, %1}, %2;" : "=f"(lo), "=f"(hi) : "l"(acc2[c][bb]));
            red[((g * 4 + c) * 7 + bb) * 33 + lane] = lo + hi;
        }
    __syncthreads();

    if (tid < 224) {
        const float* rf = red + tid * 33;
        float s0 = 0.f, s1 = 0.f, s2 = 0.f, s3 = 0.f;
#pragma unroll
        for (int q = 0; q < 32; q += 4) {
            s0 += rf[q + 0];
            s1 += rf[q + 1];
            s2 += rf[q + 2];
            s3 += rf[q + 3];
        }
        float sum = (s0 + s1) + (s2 + s3);
        int gc = tid / 7;                // g*4+c (channel within tile)
        int bb = tid - gc * 7;
        y[(i0 + gc) * 196 + a * 14 + h0 * 7 + bb] = sum;
    }
}

extern "C" void kernel_launch(void* const* d_in, const int* in_sizes, int n_in,
                              void* d_out, int out_size) {
    const float* x = (const float*)d_in[0];
    const float* w = (const float*)d_in[1];
    float* y = (float*)d_out;

    prep_kernel<<<U_BLOCKS, 256>>>(x);
    gemm_kernel<<<dim3(14, 8, 2), 256>>>(w, y);
}